// round 10
// baseline (speedup 1.0000x reference)
#include <cuda_runtime.h>
#include <cuda_bf16.h>
#include <cstdint>
#include <math.h>

#define NN    20000
#define EE    320000
#define ET    (EE + NN)
#define FIN   128
#define HID   128
#define HEADS 4
#define DBIG  (HEADS * HID)
#define BGR   64
#define SLOPE 0.2f

// ----------------------------------------------------------------------------
// Scratch (device globals)
// ----------------------------------------------------------------------------
__device__ float g_xlr[(size_t)NN * 1024];   // fused [xl | xr] output (natural order)
__device__ float g_h1[(size_t)NN * DBIG];    // K16-permuted + tf32-rounded
__device__ float g_h2[(size_t)NN * DBIG];    // K16-permuted + tf32-rounded
__device__ float g_h3[(size_t)NN * HID];     // natural
__device__ float g_xp[(size_t)NN * FIN];     // x, K16-permuted + tf32-rounded
__device__ float g_wt[1024 * 512];           // fused transposed weights (K16-permuted, tf32)
__device__ int   g_deg[NN];
__device__ int   g_off[NN + 1];
__device__ int   g_cursor[NN];
__device__ int   g_csr_src[ET];
__device__ float g_pool[BGR * HID];

// ----------------------------------------------------------------------------
// Helpers
// ----------------------------------------------------------------------------
__device__ __forceinline__ uint32_t f2tf32(float f) {
    uint32_t u;
    asm("cvt.rna.tf32.f32 %0, %1;" : "=r"(u) : "f"(f));
    return u;
}
__device__ __forceinline__ float f2tf32f(float f) { return __uint_as_float(f2tf32(f)); }
// 16-group K permutation: pos(k) = 4*(k&3) + ((k>>2)&3)  (self-inverse 4x4 transpose)
__device__ __forceinline__ int kperm16(int k) {
    return (k & ~15) | (((k & 3) << 2) | ((k >> 2) & 3));
}
__device__ __forceinline__ uint32_t smem_u32(const void* p) {
    uint32_t a;
    asm("{ .reg .u64 t; cvta.to.shared.u64 t, %1; cvt.u32.u64 %0, t; }" : "=r"(a) : "l"(p));
    return a;
}
__device__ __forceinline__ void cp_async16(uint32_t dst, const void* src) {
    asm volatile("cp.async.cg.shared.global [%0], [%1], 16;" :: "r"(dst), "l"(src) : "memory");
}
__device__ __forceinline__ void cp_commit() {
    asm volatile("cp.async.commit_group;" ::: "memory");
}
template <int N>
__device__ __forceinline__ void cp_wait() {
    asm volatile("cp.async.wait_group %0;" :: "n"(N) : "memory");
}

// ----------------------------------------------------------------------------
// CSR build
// ----------------------------------------------------------------------------
__global__ void zero_kernel() {
    int i = blockIdx.x * blockDim.x + threadIdx.x;
    if (i < NN) g_deg[i] = 0;
}
__global__ void hist_kernel(const int* __restrict__ edst) {
    int e = blockIdx.x * blockDim.x + threadIdx.x;
    if (e >= ET) return;
    int d = (e < EE) ? edst[e] : (e - EE);
    atomicAdd(&g_deg[d], 1);
}
__global__ void scan_kernel() {
    __shared__ int part[1024];
    int t = threadIdx.x;
    const int chunk = (NN + 1023) / 1024;
    int beg = t * chunk, end = beg + chunk;
    if (end > NN) end = NN;
    int s = 0;
    for (int i = beg; i < end; i++) s += g_deg[i];
    part[t] = s;
    __syncthreads();
    for (int o = 1; o < 1024; o <<= 1) {
        int v = (t >= o) ? part[t - o] : 0;
        __syncthreads();
        part[t] += v;
        __syncthreads();
    }
    int run = (t == 0) ? 0 : part[t - 1];
    for (int i = beg; i < end; i++) {
        g_off[i] = run; g_cursor[i] = run; run += g_deg[i];
    }
    if (t == 1023) g_off[NN] = part[1023];
}
__global__ void scatter_kernel(const int* __restrict__ esrc, const int* __restrict__ edst) {
    int e = blockIdx.x * blockDim.x + threadIdx.x;
    if (e >= ET) return;
    int s, d;
    if (e < EE) { s = esrc[e]; d = edst[e]; }
    else        { s = e - EE;  d = e - EE; }
    int pos = atomicAdd(&g_cursor[d], 1);
    g_csr_src[pos] = s;
}

// ----------------------------------------------------------------------------
// x pre-pass: 16-group permute + round to tf32
// ----------------------------------------------------------------------------
__global__ void permute_x_kernel(const float* __restrict__ x, float* __restrict__ xp) {
    int idx = blockIdx.x * blockDim.x + threadIdx.x;
    if (idx >= NN * FIN) return;
    int row = idx >> 7, k = idx & 127;
    xp[(size_t)row * FIN + kperm16(k)] = f2tf32f(x[idx]);
}

// ----------------------------------------------------------------------------
// Weight transpose: WT[m][kperm16(k)] = tf32(W[k][m])
// ----------------------------------------------------------------------------
__global__ void transpose_kernel(const float* __restrict__ W, float* __restrict__ WT,
                                 int K, int M) {
    __shared__ float t[32][33];
    int m0 = blockIdx.x * 32, k0 = blockIdx.y * 32;
    int tx = threadIdx.x, ty = threadIdx.y;
#pragma unroll
    for (int i = 0; i < 32; i += 8)
        t[ty + i][tx] = W[(size_t)(k0 + ty + i) * M + m0 + tx];
    __syncthreads();
    int kp = kperm16(k0 + tx);
#pragma unroll
    for (int i = 0; i < 32; i += 8)
        WT[(size_t)(m0 + ty + i) * K + kp] = f2tf32f(t[tx][ty + i]);
}

// ----------------------------------------------------------------------------
// tf32 mma.sync GEMM. Block 128x128, warp tile 64x32, 8 warps, 2 CTAs/SM.
// (unchanged from R9: chunk-XOR swizzled smem, LDS.128 dual-kk fragments)
// ----------------------------------------------------------------------------
#define SMEM_A_TILE (128 * 32)
#define SMEM_B_TILE (128 * 32)
__global__ __launch_bounds__(256, 2)
void gemm_mma(const float* __restrict__ A, const float* __restrict__ BT,
              const float* __restrict__ bias_l, const float* __restrict__ bias_r,
              float* __restrict__ C, int Nrows, int K, int Mout, int Mhalf) {
    extern __shared__ float sm[];
    float* smA = sm;                       // [2][128][32]
    float* smB = sm + 2 * SMEM_A_TILE;     // [2][128][32]
    uint32_t uA = smem_u32(smA);
    uint32_t uB = smem_u32(smB);

    int tid = threadIdx.x;
    int lane = tid & 31, wid = tid >> 5;
    int wm = wid & 1;
    int wn = wid >> 1;
    int g = lane >> 2, t = lane & 3;
    int brow = blockIdx.x * 128;
    int bcol = blockIdx.y * 128;

    int cprow = tid >> 3;
    int cc = tid & 7;
    int pch = cc ^ (4 * (cprow & 1));

    float acc[4][4][4];
#pragma unroll
    for (int a = 0; a < 4; a++)
#pragma unroll
        for (int b = 0; b < 4; b++)
#pragma unroll
            for (int c = 0; c < 4; c++) acc[a][b][c] = 0.f;

    const int NT = K >> 5;

    auto load_tile = [&](int kt, int buf) {
        int k0 = kt << 5;
#pragma unroll
        for (int i = 0; i < 4; i++) {
            int row = cprow + i * 32;
            int gr = brow + row; if (gr >= Nrows) gr = Nrows - 1;
            cp_async16(uA + (uint32_t)(buf * SMEM_A_TILE + row * 32 + 4 * pch) * 4,
                       A + (size_t)gr * K + k0 + cc * 4);
        }
#pragma unroll
        for (int i = 0; i < 4; i++) {
            int row = cprow + i * 32;
            cp_async16(uB + (uint32_t)(buf * SMEM_B_TILE + row * 32 + 4 * pch) * 4,
                       BT + (size_t)(bcol + row) * K + k0 + cc * 4);
        }
    };

    load_tile(0, 0);
    cp_commit();

    for (int kt = 0; kt < NT; kt++) {
        int buf = kt & 1;
        if (kt + 1 < NT) {
            load_tile(kt + 1, (kt + 1) & 1);
            cp_commit();
            cp_wait<1>();
        } else {
            cp_wait<0>();
        }
        __syncthreads();

        const float* Ab = smA + buf * SMEM_A_TILE;
        const float* Bb = smB + buf * SMEM_B_TILE;
#pragma unroll
        for (int kb = 0; kb < 2; kb++) {
            int chb = kb * 4 + t;
            uint4 bfv[4];
#pragma unroll
            for (int nt = 0; nt < 4; nt++) {
                int n = wn * 32 + nt * 8 + g;
                bfv[nt] = *(const uint4*)(Bb + n * 32 + 4 * (chb ^ (4 * (n & 1))));
            }
#pragma unroll
            for (int mt = 0; mt < 4; mt++) {
                int r = wm * 64 + mt * 16 + g;
                int chA = chb ^ (4 * (r & 1));
                uint4 lo = *(const uint4*)(Ab + r * 32 + 4 * chA);
                uint4 hi = *(const uint4*)(Ab + (r + 8) * 32 + 4 * chA);
#pragma unroll
                for (int nt = 0; nt < 4; nt++) {
                    asm volatile(
                        "mma.sync.aligned.m16n8k8.row.col.f32.tf32.tf32.f32 "
                        "{%0,%1,%2,%3}, {%4,%5,%6,%7}, {%8,%9}, {%0,%1,%2,%3};"
                        : "+f"(acc[mt][nt][0]), "+f"(acc[mt][nt][1]),
                          "+f"(acc[mt][nt][2]), "+f"(acc[mt][nt][3])
                        : "r"(lo.x), "r"(hi.x), "r"(lo.y), "r"(hi.y),
                          "r"(bfv[nt].x), "r"(bfv[nt].y));
                    asm volatile(
                        "mma.sync.aligned.m16n8k8.row.col.f32.tf32.tf32.f32 "
                        "{%0,%1,%2,%3}, {%4,%5,%6,%7}, {%8,%9}, {%0,%1,%2,%3};"
                        : "+f"(acc[mt][nt][0]), "+f"(acc[mt][nt][1]),
                          "+f"(acc[mt][nt][2]), "+f"(acc[mt][nt][3])
                        : "r"(lo.z), "r"(hi.z), "r"(lo.w), "r"(hi.w),
                          "r"(bfv[nt].z), "r"(bfv[nt].w));
                }
            }
        }
        __syncthreads();
    }

#pragma unroll
    for (int mt = 0; mt < 4; mt++) {
        int r0 = brow + wm * 64 + mt * 16 + g;
#pragma unroll
        for (int nt = 0; nt < 4; nt++) {
            int c = bcol + wn * 32 + nt * 8 + 2 * t;
            float b0, b1;
            if (c < Mhalf) { b0 = bias_l[c]; b1 = bias_l[c + 1]; }
            else           { b0 = bias_r[c - Mhalf]; b1 = bias_r[c - Mhalf + 1]; }
            if (r0 < Nrows) {
                float2 v = make_float2(acc[mt][nt][0] + b0, acc[mt][nt][1] + b1);
                *(float2*)(C + (size_t)r0 * Mout + c) = v;
            }
            if (r0 + 8 < Nrows) {
                float2 v = make_float2(acc[mt][nt][2] + b0, acc[mt][nt][3] + b1);
                *(float2*)(C + (size_t)(r0 + 8) * Mout + c) = v;
            }
        }
    }
}

// ----------------------------------------------------------------------------
// GATv2 attention, H=4, ONE warp per node. Lane owns channels [16L, 16L+16)
// (head = L>>3). Logits for all 4 heads reduced in ONE depth-3 intra-group
// shfl tree. 2-edge ILP. PERM: in-register kperm16 regroup (no shuffles).
// ----------------------------------------------------------------------------
template <bool PERM>
__global__ __launch_bounds__(256)
void gatv2_h4(const float* __restrict__ xlr,
              const float* __restrict__ att, const float* __restrict__ bias,
              float* __restrict__ out) {
    const int S = 1024, D = 512;
    int node = blockIdx.x * 8 + (threadIdx.x >> 5);
    if (node >= NN) return;
    int lane = threadIdx.x & 31;
    int ch0 = lane * 16;

    float rv[16], av[16], acc[16];
#pragma unroll
    for (int i = 0; i < 16; i += 4) {
        *(float4*)(rv + i) = *(const float4*)(xlr + (size_t)node * S + D + ch0 + i);
        *(float4*)(av + i) = *(const float4*)(att + ch0 + i);
        acc[i] = acc[i + 1] = acc[i + 2] = acc[i + 3] = 0.f;
    }
    int s = g_off[node], e = g_off[node + 1];
    float m = -1e30f, den = 0.f;

    int j = s;
    for (; j + 2 <= e; j += 2) {
        int s0 = g_csr_src[j], s1 = g_csr_src[j + 1];
        float x0[16], x1[16];
#pragma unroll
        for (int i = 0; i < 16; i += 4) {
            *(float4*)(x0 + i) = *(const float4*)(xlr + (size_t)s0 * S + ch0 + i);
            *(float4*)(x1 + i) = *(const float4*)(xlr + (size_t)s1 * S + ch0 + i);
        }
        float p0 = 0.f, p1 = 0.f;
#pragma unroll
        for (int i = 0; i < 16; i++) {
            float t0 = x0[i] + rv[i]; t0 = t0 > 0.f ? t0 : SLOPE * t0; p0 += av[i] * t0;
            float t1 = x1[i] + rv[i]; t1 = t1 > 0.f ? t1 : SLOPE * t1; p1 += av[i] * t1;
        }
#pragma unroll
        for (int o = 4; o; o >>= 1) {
            p0 += __shfl_xor_sync(0xffffffffu, p0, o);
            p1 += __shfl_xor_sync(0xffffffffu, p1, o);
        }
        float mm = fmaxf(m, fmaxf(p0, p1));
        float sc = __expf(m - mm);
        m = mm;
        den *= sc;
        float w0 = __expf(p0 - m), w1 = __expf(p1 - m);
        den += w0 + w1;
#pragma unroll
        for (int i = 0; i < 16; i++) acc[i] = acc[i] * sc + w0 * x0[i] + w1 * x1[i];
    }
    if (j < e) {
        int s0 = g_csr_src[j];
        float x0[16];
#pragma unroll
        for (int i = 0; i < 16; i += 4)
            *(float4*)(x0 + i) = *(const float4*)(xlr + (size_t)s0 * S + ch0 + i);
        float p0 = 0.f;
#pragma unroll
        for (int i = 0; i < 16; i++) {
            float t0 = x0[i] + rv[i]; t0 = t0 > 0.f ? t0 : SLOPE * t0; p0 += av[i] * t0;
        }
#pragma unroll
        for (int o = 4; o; o >>= 1) p0 += __shfl_xor_sync(0xffffffffu, p0, o);
        float mm = fmaxf(m, p0);
        float sc = __expf(m - mm);
        m = mm;
        den *= sc;
        float w0 = __expf(p0 - m);
        den += w0;
#pragma unroll
        for (int i = 0; i < 16; i++) acc[i] = acc[i] * sc + w0 * x0[i];
    }

    float inv = 1.f / den;
    float o16[16];
#pragma unroll
    for (int i = 0; i < 16; i++) {
        float v = acc[i] * inv + bias[ch0 + i];
        o16[i] = v > 0.f ? v : expm1f(v);
    }
    float* dst = out + (size_t)node * D + ch0;
    if (PERM) {
        // kperm16 within the lane-owned 16-block: float4 p = {o[p],o[p+4],o[p+8],o[p+12]}
#pragma unroll
        for (int p = 0; p < 4; p++) {
            float4 w4 = make_float4(f2tf32f(o16[p]), f2tf32f(o16[p + 4]),
                                    f2tf32f(o16[p + 8]), f2tf32f(o16[p + 12]));
            *(float4*)(dst + 4 * p) = w4;
        }
    } else {
#pragma unroll
        for (int p = 0; p < 4; p++)
            *(float4*)(dst + 4 * p) = make_float4(o16[4 * p], o16[4 * p + 1],
                                                  o16[4 * p + 2], o16[4 * p + 3]);
    }
}

// ----------------------------------------------------------------------------
// GATv2 attention H=1 (layer 3): one warp per node, full-warp reduce.
// ----------------------------------------------------------------------------
__global__ __launch_bounds__(256)
void gatv2_h1(const float* __restrict__ xlr,
              const float* __restrict__ att, const float* __restrict__ bias,
              float* __restrict__ out) {
    const int S = 256, D = 128;
    int node = blockIdx.x * 8 + (threadIdx.x >> 5);
    if (node >= NN) return;
    int lane = threadIdx.x & 31;
    int cbase = lane * 4;

    float4 rv = *(const float4*)(xlr + (size_t)node * S + D + cbase);
    float4 av = *(const float4*)(att + cbase);
    int s = g_off[node], e = g_off[node + 1];

    float m = -1e30f, den = 0.f;
    float4 acc = make_float4(0.f, 0.f, 0.f, 0.f);

    int j = s;
    for (; j + 2 <= e; j += 2) {
        int s0 = g_csr_src[j], s1 = g_csr_src[j + 1];
        float4 x0 = *(const float4*)(xlr + (size_t)s0 * S + cbase);
        float4 x1 = *(const float4*)(xlr + (size_t)s1 * S + cbase);
        float t0, t1, p0 = 0.f, p1 = 0.f;
        t0 = x0.x + rv.x; t0 = t0 > 0.f ? t0 : SLOPE * t0; p0 += av.x * t0;
        t1 = x1.x + rv.x; t1 = t1 > 0.f ? t1 : SLOPE * t1; p1 += av.x * t1;
        t0 = x0.y + rv.y; t0 = t0 > 0.f ? t0 : SLOPE * t0; p0 += av.y * t0;
        t1 = x1.y + rv.y; t1 = t1 > 0.f ? t1 : SLOPE * t1; p1 += av.y * t1;
        t0 = x0.z + rv.z; t0 = t0 > 0.f ? t0 : SLOPE * t0; p0 += av.z * t0;
        t1 = x1.z + rv.z; t1 = t1 > 0.f ? t1 : SLOPE * t1; p1 += av.z * t1;
        t0 = x0.w + rv.w; t0 = t0 > 0.f ? t0 : SLOPE * t0; p0 += av.w * t0;
        t1 = x1.w + rv.w; t1 = t1 > 0.f ? t1 : SLOPE * t1; p1 += av.w * t1;
#pragma unroll
        for (int o = 16; o; o >>= 1) {
            p0 += __shfl_xor_sync(0xffffffffu, p0, o);
            p1 += __shfl_xor_sync(0xffffffffu, p1, o);
        }
        float mm = fmaxf(m, fmaxf(p0, p1));
        float sc = __expf(m - mm);
        m = mm;
        den *= sc; acc.x *= sc; acc.y *= sc; acc.z *= sc; acc.w *= sc;
        float w0 = __expf(p0 - m), w1 = __expf(p1 - m);
        den += w0 + w1;
        acc.x += w0 * x0.x + w1 * x1.x;
        acc.y += w0 * x0.y + w1 * x1.y;
        acc.z += w0 * x0.z + w1 * x1.z;
        acc.w += w0 * x0.w + w1 * x1.w;
    }
    if (j < e) {
        int s0 = g_csr_src[j];
        float4 x0 = *(const float4*)(xlr + (size_t)s0 * S + cbase);
        float t0, p0 = 0.f;
        t0 = x0.x + rv.x; t0 = t0 > 0.f ? t0 : SLOPE * t0; p0 += av.x * t0;
        t0 = x0.y + rv.y; t0 = t0 > 0.f ? t0 : SLOPE * t0; p0 += av.y * t0;
        t0 = x0.z + rv.z; t0 = t0 > 0.f ? t0 : SLOPE * t0; p0 += av.z * t0;
        t0 = x0.w + rv.w; t0 = t0 > 0.f ? t0 : SLOPE * t0; p0 += av.w * t0;
#pragma unroll
        for (int o = 16; o; o >>= 1) p0 += __shfl_xor_sync(0xffffffffu, p0, o);
        float mm = fmaxf(m, p0);
        float sc = __expf(m - mm);
        m = mm;
        den *= sc; acc.x *= sc; acc.y *= sc; acc.z *= sc; acc.w *= sc;
        float w0 = __expf(p0 - m);
        den += w0;
        acc.x += w0 * x0.x; acc.y += w0 * x0.y; acc.z += w0 * x0.z; acc.w += w0 * x0.w;
    }

    float inv = 1.f / den;
    float4 o4;
    float v;
    v = acc.x * inv + bias[cbase + 0]; o4.x = v > 0.f ? v : expm1f(v);
    v = acc.y * inv + bias[cbase + 1]; o4.y = v > 0.f ? v : expm1f(v);
    v = acc.z * inv + bias[cbase + 2]; o4.z = v > 0.f ? v : expm1f(v);
    v = acc.w * inv + bias[cbase + 3]; o4.w = v > 0.f ? v : expm1f(v);
    *(float4*)(out + (size_t)node * D + cbase) = o4;
}

// ----------------------------------------------------------------------------
// Pooling (batch sorted -> contiguous segments) + MLP
// ----------------------------------------------------------------------------
__global__ void pool_kernel(const int* __restrict__ batch) {
    int g = blockIdx.x;
    int t = threadIdx.x;
    __shared__ int seg[2];
    if (t < 2) {
        int target = g + t;
        int lo = 0, hi = NN;
        while (lo < hi) {
            int mid = (lo + hi) >> 1;
            if (batch[mid] < target) lo = mid + 1; else hi = mid;
        }
        seg[t] = lo;
    }
    __syncthreads();
    int lo = seg[0], hi = seg[1];
    float sum = 0.f;
    for (int i = lo; i < hi; i++) sum += g_h3[(size_t)i * HID + t];
    float c = fmaxf((float)(hi - lo), 1.0f);
    g_pool[g * HID + t] = sum / c;
}
__global__ void mlp_kernel(const float* __restrict__ W1, const float* __restrict__ b1,
                           const float* __restrict__ W2, const float* __restrict__ b2,
                           float* __restrict__ out) {
    int g = blockIdx.x;
    int t = threadIdx.x;
    __shared__ float p[HID];
    __shared__ float hid[HID];
    __shared__ float red[HID];
    p[t] = g_pool[g * HID + t];
    __syncthreads();
    float a = 0.f;
    for (int k = 0; k < HID; k++) a += p[k] * W1[k * HID + t];
    hid[t] = fmaxf(a + b1[t], 0.f);
    __syncthreads();
    for (int o = 0; o < 2; o++) {
        red[t] = hid[t] * W2[t * 2 + o];
        __syncthreads();
        for (int stp = 64; stp; stp >>= 1) {
            if (t < stp) red[t] += red[t + stp];
            __syncthreads();
        }
        if (t == 0) out[g * 2 + o] = red[0] + b2[o];
        __syncthreads();
    }
}

// ----------------------------------------------------------------------------
// Launch
// ----------------------------------------------------------------------------
extern "C" void kernel_launch(void* const* d_in, const int* in_sizes, int n_in,
                              void* d_out, int out_size) {
    const float* x     = (const float*)d_in[0];
    const int*   esrc  = (const int*)d_in[1];
    const int*   edst  = (const int*)d_in[2];
    const int*   batch = (const int*)d_in[3];
    const float* Wl1 = (const float*)d_in[4];
    const float* Wr1 = (const float*)d_in[5];
    const float* bl1 = (const float*)d_in[6];
    const float* br1 = (const float*)d_in[7];
    const float* att1  = (const float*)d_in[8];
    const float* bias1 = (const float*)d_in[9];
    const float* Wl2 = (const float*)d_in[10];
    const float* Wr2 = (const float*)d_in[11];
    const float* bl2 = (const float*)d_in[12];
    const float* br2 = (const float*)d_in[13];
    const float* att2  = (const float*)d_in[14];
    const float* bias2 = (const float*)d_in[15];
    const float* Wl3 = (const float*)d_in[16];
    const float* Wr3 = (const float*)d_in[17];
    const float* bl3 = (const float*)d_in[18];
    const float* br3 = (const float*)d_in[19];
    const float* att3  = (const float*)d_in[20];
    const float* bias3 = (const float*)d_in[21];
    const float* Wm1 = (const float*)d_in[22];
    const float* bm1 = (const float*)d_in[23];
    const float* Wm2 = (const float*)d_in[24];
    const float* bm2 = (const float*)d_in[25];
    float* out = (float*)d_out;

    float *p_xlr, *p_h1, *p_h2, *p_h3, *p_xp, *p_wt;
    cudaGetSymbolAddress((void**)&p_xlr, g_xlr);
    cudaGetSymbolAddress((void**)&p_h1, g_h1);
    cudaGetSymbolAddress((void**)&p_h2, g_h2);
    cudaGetSymbolAddress((void**)&p_h3, g_h3);
    cudaGetSymbolAddress((void**)&p_xp, g_xp);
    cudaGetSymbolAddress((void**)&p_wt, g_wt);

    const int SMEM = 2 * (SMEM_A_TILE + SMEM_B_TILE) * 4;  // 65536 bytes
    cudaFuncSetAttribute(gemm_mma, cudaFuncAttributeMaxDynamicSharedMemorySize, SMEM);

    const int RT = (NN + 127) / 128;  // 157 row tiles
    const int AB = (NN + 7) / 8;      // attention blocks (1 warp/node, 8/block)
    dim3 tb(32, 8);

    // --- front: layer-1 GEMM path first (gemm_mma at stream position 4 for ncu) ---
    permute_x_kernel<<<(NN * FIN + 255) / 256, 256>>>(x, p_xp);                 // 1
    transpose_kernel<<<dim3(16, 4), tb>>>(Wl1, p_wt, 128, 512);                 // 2
    transpose_kernel<<<dim3(16, 4), tb>>>(Wr1, p_wt + 512 * 128, 128, 512);     // 3
    gemm_mma<<<dim3(RT, 8), 256, SMEM>>>(p_xp, p_wt, bl1, br1, p_xlr,           // 4
                                         NN, 128, 1024, 512);

    // --- CSR build (only needed before attention) ---
    zero_kernel<<<(NN + 255) / 256, 256>>>();
    hist_kernel<<<(ET + 255) / 256, 256>>>(edst);
    scan_kernel<<<1, 1024>>>();
    scatter_kernel<<<(ET + 255) / 256, 256>>>(esrc, edst);

    gatv2_h4<true><<<AB, 256>>>(p_xlr, att1, bias1, p_h1);

    // Layer 2
    transpose_kernel<<<dim3(16, 16), tb>>>(Wl2, p_wt, 512, 512);
    transpose_kernel<<<dim3(16, 16), tb>>>(Wr2, p_wt + 512 * 512, 512, 512);
    gemm_mma<<<dim3(RT, 8), 256, SMEM>>>(p_h1, p_wt, bl2, br2, p_xlr, NN, 512, 1024, 512);
    gatv2_h4<true><<<AB, 256>>>(p_xlr, att2, bias2, p_h2);

    // Layer 3
    transpose_kernel<<<dim3(4, 16), tb>>>(Wl3, p_wt, 512, 128);
    transpose_kernel<<<dim3(4, 16), tb>>>(Wr3, p_wt + 128 * 512, 512, 128);
    gemm_mma<<<dim3(RT, 2), 256, SMEM>>>(p_h2, p_wt, bl3, br3, p_xlr, NN, 512, 256, 128);
    gatv2_h1<<<AB, 256>>>(p_xlr, att3, bias3, p_h3);

    // Pool + MLP
    pool_kernel<<<BGR, HID>>>(batch);
    mlp_kernel<<<BGR, HID>>>(Wm1, bm1, Wm2, bm2, out);
}

// round 11
// speedup vs baseline: 1.3686x; 1.3686x over previous
#include <cuda_runtime.h>
#include <cuda_fp16.h>
#include <cstdint>
#include <math.h>

#define NN    20000
#define EE    320000
#define ET    (EE + NN)
#define FIN   128
#define HID   128
#define HEADS 4
#define DBIG  (HEADS * HID)
#define BGR   64
#define SLOPE 0.2f

// ----------------------------------------------------------------------------
// Scratch (device globals)
// ----------------------------------------------------------------------------
__device__ float  g_xlr[(size_t)NN * 1024];  // fused [xl | xr] GEMM output (fp32, natural)
__device__ __half g_h1[(size_t)NN * DBIG];   // pair-permuted fp16 (GEMM input)
__device__ __half g_h2[(size_t)NN * DBIG];   // pair-permuted fp16 (GEMM input)
__device__ float  g_h3[(size_t)NN * HID];    // natural fp32
__device__ __half g_xp[(size_t)NN * FIN];    // x, pair-permuted fp16
__device__ __half g_wt[1024 * 512];          // fused transposed weights, pair-permuted fp16
__device__ int    g_deg[NN];
__device__ int    g_off[NN + 1];
__device__ int    g_cursor[NN];
__device__ int    g_csr_src[ET];
__device__ float  g_pool[BGR * HID];

// ----------------------------------------------------------------------------
// Helpers
// ----------------------------------------------------------------------------
// pair permutation within a 16-pair (32-k) group: q = 4*(p&3) + (p>>2)
__device__ __forceinline__ int pairperm(int p) { return ((p & 3) << 2) | (p >> 2); }
// position of logical k within pair-permuted 32-group layout
__device__ __forceinline__ int kpos(int k) {
    return (k & ~31) | (pairperm((k >> 1) & 15) << 1) | (k & 1);
}
__device__ __forceinline__ uint32_t smem_u32(const void* p) {
    uint32_t a;
    asm("{ .reg .u64 t; cvta.to.shared.u64 t, %1; cvt.u32.u64 %0, t; }" : "=r"(a) : "l"(p));
    return a;
}
__device__ __forceinline__ void cp_async16(uint32_t dst, const void* src) {
    asm volatile("cp.async.cg.shared.global [%0], [%1], 16;" :: "r"(dst), "l"(src) : "memory");
}
__device__ __forceinline__ void cp_commit() {
    asm volatile("cp.async.commit_group;" ::: "memory");
}
template <int N>
__device__ __forceinline__ void cp_wait() {
    asm volatile("cp.async.wait_group %0;" :: "n"(N) : "memory");
}

// ----------------------------------------------------------------------------
// CSR build
// ----------------------------------------------------------------------------
__global__ void zero_kernel() {
    int i = blockIdx.x * blockDim.x + threadIdx.x;
    if (i < NN) g_deg[i] = 0;
}
__global__ void hist_kernel(const int* __restrict__ edst) {
    int e = blockIdx.x * blockDim.x + threadIdx.x;
    if (e >= ET) return;
    int d = (e < EE) ? edst[e] : (e - EE);
    atomicAdd(&g_deg[d], 1);
}
__global__ void scan_kernel() {
    __shared__ int part[1024];
    int t = threadIdx.x;
    const int chunk = (NN + 1023) / 1024;
    int beg = t * chunk, end = beg + chunk;
    if (end > NN) end = NN;
    int s = 0;
    for (int i = beg; i < end; i++) s += g_deg[i];
    part[t] = s;
    __syncthreads();
    for (int o = 1; o < 1024; o <<= 1) {
        int v = (t >= o) ? part[t - o] : 0;
        __syncthreads();
        part[t] += v;
        __syncthreads();
    }
    int run = (t == 0) ? 0 : part[t - 1];
    for (int i = beg; i < end; i++) {
        g_off[i] = run; g_cursor[i] = run; run += g_deg[i];
    }
    if (t == 1023) g_off[NN] = part[1023];
}
__global__ void scatter_kernel(const int* __restrict__ esrc, const int* __restrict__ edst) {
    int e = blockIdx.x * blockDim.x + threadIdx.x;
    if (e >= ET) return;
    int s, d;
    if (e < EE) { s = esrc[e]; d = edst[e]; }
    else        { s = e - EE;  d = e - EE; }
    int pos = atomicAdd(&g_cursor[d], 1);
    g_csr_src[pos] = s;
}

// ----------------------------------------------------------------------------
// x pre-pass: pair-permute + convert to fp16
// ----------------------------------------------------------------------------
__global__ void permute_x_kernel(const float* __restrict__ x, __half* __restrict__ xp) {
    int idx = blockIdx.x * blockDim.x + threadIdx.x;
    if (idx >= NN * FIN) return;
    int row = idx >> 7, k = idx & 127;
    xp[(size_t)row * FIN + kpos(k)] = __float2half_rn(x[idx]);
}

// ----------------------------------------------------------------------------
// Weight transpose: WT[m][kpos(k)] = fp16(W[k][m])
// ----------------------------------------------------------------------------
__global__ void transpose_kernel(const float* __restrict__ W, __half* __restrict__ WT,
                                 int K, int M) {
    __shared__ float t[32][33];
    int m0 = blockIdx.x * 32, k0 = blockIdx.y * 32;
    int tx = threadIdx.x, ty = threadIdx.y;
#pragma unroll
    for (int i = 0; i < 32; i += 8)
        t[ty + i][tx] = W[(size_t)(k0 + ty + i) * M + m0 + tx];
    __syncthreads();
    int kp = k0 + kpos(tx);   // k0 is a multiple of 32
#pragma unroll
    for (int i = 0; i < 32; i += 8)
        WT[(size_t)(m0 + ty + i) * K + kp] = __float2half_rn(t[tx][ty + i]);
}

// ----------------------------------------------------------------------------
// fp16 mma.sync m16n8k16 GEMM, fp32 accumulate. Block 128x128, warp 64x32,
// 8 warps, 2 CTAs/SM, cp.async double-buffered. Smem rows = 32 halves (64B),
// pair-permuted so one LDS.128 per row feeds BOTH k16-steps of a 32-k tile.
// ----------------------------------------------------------------------------
#define SMEM_A_TILE (128 * 32)   // halves
#define SMEM_B_TILE (128 * 32)   // halves
__global__ __launch_bounds__(256, 2)
void gemm_mma(const __half* __restrict__ A, const __half* __restrict__ BT,
              const float* __restrict__ bias_l, const float* __restrict__ bias_r,
              float* __restrict__ C, int Nrows, int K, int Mout, int Mhalf) {
    extern __shared__ __half smh[];
    __half* smA = smh;                      // [2][128][32]
    __half* smB = smh + 2 * SMEM_A_TILE;    // [2][128][32]
    uint32_t uA = smem_u32(smA);
    uint32_t uB = smem_u32(smB);

    int tid = threadIdx.x;
    int lane = tid & 31, wid = tid >> 5;
    int wm = wid & 1;        // M offset 64*wm
    int wn = wid >> 1;       // N offset 32*wn
    int g = lane >> 2, t = lane & 3;
    int brow = blockIdx.x * 128;
    int bcol = blockIdx.y * 128;

    int cprow = tid >> 2;            // 0..63, two passes of 64 rows
    int cc = tid & 3;                // 16B chunk within 64B row

    float acc[4][4][4];
#pragma unroll
    for (int a = 0; a < 4; a++)
#pragma unroll
        for (int b = 0; b < 4; b++)
#pragma unroll
            for (int c = 0; c < 4; c++) acc[a][b][c] = 0.f;

    const int NT = K >> 5;

    auto load_tile = [&](int kt, int buf) {
        int k0 = kt << 5;
#pragma unroll
        for (int i = 0; i < 2; i++) {
            int row = cprow + i * 64;
            int gr = brow + row; if (gr >= Nrows) gr = Nrows - 1;
            cp_async16(uA + (uint32_t)(buf * SMEM_A_TILE + row * 32 + cc * 8) * 2,
                       A + (size_t)gr * K + k0 + cc * 8);
        }
#pragma unroll
        for (int i = 0; i < 2; i++) {
            int row = cprow + i * 64;
            cp_async16(uB + (uint32_t)(buf * SMEM_B_TILE + row * 32 + cc * 8) * 2,
                       BT + (size_t)(bcol + row) * K + k0 + cc * 8);
        }
    };

    load_tile(0, 0);
    cp_commit();

    for (int kt = 0; kt < NT; kt++) {
        int buf = kt & 1;
        if (kt + 1 < NT) {
            load_tile(kt + 1, (kt + 1) & 1);
            cp_commit();
            cp_wait<1>();
        } else {
            cp_wait<0>();
        }
        __syncthreads();

        const __half* Ab = smA + buf * SMEM_A_TILE;
        const __half* Bb = smB + buf * SMEM_B_TILE;

        uint4 bfv[4];
#pragma unroll
        for (int nt = 0; nt < 4; nt++) {
            int n = wn * 32 + nt * 8 + g;
            bfv[nt] = *(const uint4*)(Bb + n * 32 + t * 8);
        }
#pragma unroll
        for (int mt = 0; mt < 4; mt++) {
            int r = wm * 64 + mt * 16 + g;
            uint4 lo = *(const uint4*)(Ab + r * 32 + t * 8);
            uint4 hi = *(const uint4*)(Ab + (r + 8) * 32 + t * 8);
#pragma unroll
            for (int nt = 0; nt < 4; nt++) {
                // k16-step 0: pairs {t, t+4}
                asm volatile(
                    "mma.sync.aligned.m16n8k16.row.col.f32.f16.f16.f32 "
                    "{%0,%1,%2,%3}, {%4,%5,%6,%7}, {%8,%9}, {%0,%1,%2,%3};"
                    : "+f"(acc[mt][nt][0]), "+f"(acc[mt][nt][1]),
                      "+f"(acc[mt][nt][2]), "+f"(acc[mt][nt][3])
                    : "r"(lo.x), "r"(hi.x), "r"(lo.y), "r"(hi.y),
                      "r"(bfv[nt].x), "r"(bfv[nt].y));
                // k16-step 1: pairs {t+8, t+12}
                asm volatile(
                    "mma.sync.aligned.m16n8k16.row.col.f32.f16.f16.f32 "
                    "{%0,%1,%2,%3}, {%4,%5,%6,%7}, {%8,%9}, {%0,%1,%2,%3};"
                    : "+f"(acc[mt][nt][0]), "+f"(acc[mt][nt][1]),
                      "+f"(acc[mt][nt][2]), "+f"(acc[mt][nt][3])
                    : "r"(lo.z), "r"(hi.z), "r"(lo.w), "r"(hi.w),
                      "r"(bfv[nt].z), "r"(bfv[nt].w));
            }
        }
        __syncthreads();
    }

#pragma unroll
    for (int mt = 0; mt < 4; mt++) {
        int r0 = brow + wm * 64 + mt * 16 + g;
#pragma unroll
        for (int nt = 0; nt < 4; nt++) {
            int c = bcol + wn * 32 + nt * 8 + 2 * t;
            float b0, b1;
            if (c < Mhalf) { b0 = bias_l[c]; b1 = bias_l[c + 1]; }
            else           { b0 = bias_r[c - Mhalf]; b1 = bias_r[c - Mhalf + 1]; }
            if (r0 < Nrows) {
                float2 v = make_float2(acc[mt][nt][0] + b0, acc[mt][nt][1] + b1);
                *(float2*)(C + (size_t)r0 * Mout + c) = v;
            }
            if (r0 + 8 < Nrows) {
                float2 v = make_float2(acc[mt][nt][2] + b0, acc[mt][nt][3] + b1);
                *(float2*)(C + (size_t)(r0 + 8) * Mout + c) = v;
            }
        }
    }
}

// ----------------------------------------------------------------------------
// Fused GATv2 attention (online softmax), 2-edge ILP: one warp per (node, head).
// PERM: write pair-permuted fp16 (next GEMM's A layout); else natural fp32.
// ----------------------------------------------------------------------------
template <int H, bool PERM>
__global__ __launch_bounds__(256)
void gatv2_fused(const float* __restrict__ xlr,
                 const float* __restrict__ att, const float* __restrict__ bias,
                 void* __restrict__ outp) {
    const int S = 2 * H * 128;
    const int D = H * 128;
    int wg = blockIdx.x * 8 + (threadIdx.x >> 5);
    int node = wg / H;
    int h = wg % H;
    if (node >= NN) return;
    int lane = threadIdx.x & 31;
    int cbase = h * 128 + lane * 4;

    float4 rv = *(const float4*)(xlr + (size_t)node * S + D + cbase);
    float4 av = *(const float4*)(att + cbase);
    int s = g_off[node], e = g_off[node + 1];

    float m = -1e30f, den = 0.f;
    float4 acc = make_float4(0.f, 0.f, 0.f, 0.f);

    int j = s;
    for (; j + 2 <= e; j += 2) {
        int s0 = g_csr_src[j], s1 = g_csr_src[j + 1];
        float4 x0 = *(const float4*)(xlr + (size_t)s0 * S + cbase);
        float4 x1 = *(const float4*)(xlr + (size_t)s1 * S + cbase);
        float t0, t1, p0 = 0.f, p1 = 0.f;
        t0 = x0.x + rv.x; t0 = t0 > 0.f ? t0 : SLOPE * t0; p0 += av.x * t0;
        t1 = x1.x + rv.x; t1 = t1 > 0.f ? t1 : SLOPE * t1; p1 += av.x * t1;
        t0 = x0.y + rv.y; t0 = t0 > 0.f ? t0 : SLOPE * t0; p0 += av.y * t0;
        t1 = x1.y + rv.y; t1 = t1 > 0.f ? t1 : SLOPE * t1; p1 += av.y * t1;
        t0 = x0.z + rv.z; t0 = t0 > 0.f ? t0 : SLOPE * t0; p0 += av.z * t0;
        t1 = x1.z + rv.z; t1 = t1 > 0.f ? t1 : SLOPE * t1; p1 += av.z * t1;
        t0 = x0.w + rv.w; t0 = t0 > 0.f ? t0 : SLOPE * t0; p0 += av.w * t0;
        t1 = x1.w + rv.w; t1 = t1 > 0.f ? t1 : SLOPE * t1; p1 += av.w * t1;
#pragma unroll
        for (int o = 16; o; o >>= 1) {
            p0 += __shfl_xor_sync(0xffffffffu, p0, o);
            p1 += __shfl_xor_sync(0xffffffffu, p1, o);
        }
        float mm = fmaxf(m, fmaxf(p0, p1));
        float sc = __expf(m - mm);
        m = mm;
        den *= sc; acc.x *= sc; acc.y *= sc; acc.z *= sc; acc.w *= sc;
        float w0 = __expf(p0 - m), w1 = __expf(p1 - m);
        den += w0 + w1;
        acc.x += w0 * x0.x + w1 * x1.x;
        acc.y += w0 * x0.y + w1 * x1.y;
        acc.z += w0 * x0.z + w1 * x1.z;
        acc.w += w0 * x0.w + w1 * x1.w;
    }
    if (j < e) {
        int s0 = g_csr_src[j];
        float4 x0 = *(const float4*)(xlr + (size_t)s0 * S + cbase);
        float t0, p0 = 0.f;
        t0 = x0.x + rv.x; t0 = t0 > 0.f ? t0 : SLOPE * t0; p0 += av.x * t0;
        t0 = x0.y + rv.y; t0 = t0 > 0.f ? t0 : SLOPE * t0; p0 += av.y * t0;
        t0 = x0.z + rv.z; t0 = t0 > 0.f ? t0 : SLOPE * t0; p0 += av.z * t0;
        t0 = x0.w + rv.w; t0 = t0 > 0.f ? t0 : SLOPE * t0; p0 += av.w * t0;
#pragma unroll
        for (int o = 16; o; o >>= 1) p0 += __shfl_xor_sync(0xffffffffu, p0, o);
        float mm = fmaxf(m, p0);
        float sc = __expf(m - mm);
        m = mm;
        den *= sc; acc.x *= sc; acc.y *= sc; acc.z *= sc; acc.w *= sc;
        float w0 = __expf(p0 - m);
        den += w0;
        acc.x += w0 * x0.x; acc.y += w0 * x0.y; acc.z += w0 * x0.z; acc.w += w0 * x0.w;
    }

    float inv = 1.f / den;
    float4 o4;
    float v;
    v = acc.x * inv + bias[cbase + 0]; o4.x = v > 0.f ? v : expm1f(v);
    v = acc.y * inv + bias[cbase + 1]; o4.y = v > 0.f ? v : expm1f(v);
    v = acc.z * inv + bias[cbase + 2]; o4.z = v > 0.f ? v : expm1f(v);
    v = acc.w * inv + bias[cbase + 3]; o4.w = v > 0.f ? v : expm1f(v);

    if (PERM) {
        // lane owns pairs p0 = 2*(lane&7), p0+1 of 32-ch group (lane>>3) in head h.
        // q0 = pairperm(p0), q1 = q0 + 4 (p0 even => no wrap).
        __half* out = (__half*)outp;
        int lw = lane & 7;
        int q0 = pairperm(2 * lw);
        size_t base = (size_t)node * D + h * 128 + (lane >> 3) * 32 + 2 * q0;
        *(__half2*)(out + base)     = __floats2half2_rn(o4.x, o4.y);
        *(__half2*)(out + base + 8) = __floats2half2_rn(o4.z, o4.w);
    } else {
        float* out = (float*)outp;
        *(float4*)(out + (size_t)node * D + cbase) = o4;
    }
}

// ----------------------------------------------------------------------------
// Pooling (batch sorted -> contiguous segments) + MLP
// ----------------------------------------------------------------------------
__global__ void pool_kernel(const int* __restrict__ batch) {
    int g = blockIdx.x;
    int t = threadIdx.x;
    __shared__ int seg[2];
    if (t < 2) {
        int target = g + t;
        int lo = 0, hi = NN;
        while (lo < hi) {
            int mid = (lo + hi) >> 1;
            if (batch[mid] < target) lo = mid + 1; else hi = mid;
        }
        seg[t] = lo;
    }
    __syncthreads();
    int lo = seg[0], hi = seg[1];
    float sum = 0.f;
    for (int i = lo; i < hi; i++) sum += g_h3[(size_t)i * HID + t];
    float c = fmaxf((float)(hi - lo), 1.0f);
    g_pool[g * HID + t] = sum / c;
}
__global__ void mlp_kernel(const float* __restrict__ W1, const float* __restrict__ b1,
                           const float* __restrict__ W2, const float* __restrict__ b2,
                           float* __restrict__ out) {
    int g = blockIdx.x;
    int t = threadIdx.x;
    __shared__ float p[HID];
    __shared__ float hid[HID];
    __shared__ float red[HID];
    p[t] = g_pool[g * HID + t];
    __syncthreads();
    float a = 0.f;
    for (int k = 0; k < HID; k++) a += p[k] * W1[k * HID + t];
    hid[t] = fmaxf(a + b1[t], 0.f);
    __syncthreads();
    for (int o = 0; o < 2; o++) {
        red[t] = hid[t] * W2[t * 2 + o];
        __syncthreads();
        for (int stp = 64; stp; stp >>= 1) {
            if (t < stp) red[t] += red[t + stp];
            __syncthreads();
        }
        if (t == 0) out[g * 2 + o] = red[0] + b2[o];
        __syncthreads();
    }
}

// ----------------------------------------------------------------------------
// Launch
// ----------------------------------------------------------------------------
extern "C" void kernel_launch(void* const* d_in, const int* in_sizes, int n_in,
                              void* d_out, int out_size) {
    const float* x     = (const float*)d_in[0];
    const int*   esrc  = (const int*)d_in[1];
    const int*   edst  = (const int*)d_in[2];
    const int*   batch = (const int*)d_in[3];
    const float* Wl1 = (const float*)d_in[4];
    const float* Wr1 = (const float*)d_in[5];
    const float* bl1 = (const float*)d_in[6];
    const float* br1 = (const float*)d_in[7];
    const float* att1  = (const float*)d_in[8];
    const float* bias1 = (const float*)d_in[9];
    const float* Wl2 = (const float*)d_in[10];
    const float* Wr2 = (const float*)d_in[11];
    const float* bl2 = (const float*)d_in[12];
    const float* br2 = (const float*)d_in[13];
    const float* att2  = (const float*)d_in[14];
    const float* bias2 = (const float*)d_in[15];
    const float* Wl3 = (const float*)d_in[16];
    const float* Wr3 = (const float*)d_in[17];
    const float* bl3 = (const float*)d_in[18];
    const float* br3 = (const float*)d_in[19];
    const float* att3  = (const float*)d_in[20];
    const float* bias3 = (const float*)d_in[21];
    const float* Wm1 = (const float*)d_in[22];
    const float* bm1 = (const float*)d_in[23];
    const float* Wm2 = (const float*)d_in[24];
    const float* bm2 = (const float*)d_in[25];
    float* out = (float*)d_out;

    float *p_xlr, *p_h3;
    __half *p_h1, *p_h2, *p_xp, *p_wt;
    cudaGetSymbolAddress((void**)&p_xlr, g_xlr);
    cudaGetSymbolAddress((void**)&p_h1, g_h1);
    cudaGetSymbolAddress((void**)&p_h2, g_h2);
    cudaGetSymbolAddress((void**)&p_h3, g_h3);
    cudaGetSymbolAddress((void**)&p_xp, g_xp);
    cudaGetSymbolAddress((void**)&p_wt, g_wt);

    const int SMEM = 2 * (SMEM_A_TILE + SMEM_B_TILE) * 2;  // 32768 bytes
    cudaFuncSetAttribute(gemm_mma, cudaFuncAttributeMaxDynamicSharedMemorySize, SMEM);

    const int RT = (NN + 127) / 128;  // 157 row tiles
    dim3 tb(32, 8);

    // --- front: layer-1 GEMM path first (gemm_mma at stream position 4 for ncu) ---
    permute_x_kernel<<<(NN * FIN + 255) / 256, 256>>>(x, p_xp);                 // 1
    transpose_kernel<<<dim3(16, 4), tb>>>(Wl1, p_wt, 128, 512);                 // 2
    transpose_kernel<<<dim3(16, 4), tb>>>(Wr1, p_wt + 512 * 128, 128, 512);     // 3
    gemm_mma<<<dim3(RT, 8), 256, SMEM>>>(p_xp, p_wt, bl1, br1, p_xlr,           // 4
                                         NN, 128, 1024, 512);

    // --- CSR build (only needed before attention) ---
    zero_kernel<<<(NN + 255) / 256, 256>>>();
    hist_kernel<<<(ET + 255) / 256, 256>>>(edst);
    scan_kernel<<<1, 1024>>>();
    scatter_kernel<<<(ET + 255) / 256, 256>>>(esrc, edst);

    gatv2_fused<HEADS, true><<<(NN * HEADS + 7) / 8, 256>>>(p_xlr, att1, bias1, p_h1);

    // Layer 2
    transpose_kernel<<<dim3(16, 16), tb>>>(Wl2, p_wt, 512, 512);
    transpose_kernel<<<dim3(16, 16), tb>>>(Wr2, p_wt + 512 * 512, 512, 512);
    gemm_mma<<<dim3(RT, 8), 256, SMEM>>>(p_h1, p_wt, bl2, br2, p_xlr, NN, 512, 1024, 512);
    gatv2_fused<HEADS, true><<<(NN * HEADS + 7) / 8, 256>>>(p_xlr, att2, bias2, p_h2);

    // Layer 3
    transpose_kernel<<<dim3(4, 16), tb>>>(Wl3, p_wt, 512, 128);
    transpose_kernel<<<dim3(4, 16), tb>>>(Wr3, p_wt + 128 * 512, 512, 128);
    gemm_mma<<<dim3(RT, 2), 256, SMEM>>>(p_h2, p_wt, bl3, br3, p_xlr, NN, 512, 256, 128);
    gatv2_fused<1, false><<<(NN + 7) / 8, 256>>>(p_xlr, att3, bias3, p_h3);

    // Pool + MLP
    pool_kernel<<<BGR, HID>>>(batch);
    mlp_kernel<<<BGR, HID>>>(Wm1, bm1, Wm2, bm2, out);
}